// round 5
// baseline (speedup 1.0000x reference)
#include <cuda_runtime.h>
#include <math.h>
#include <limits.h>
#include <stdint.h>

// ---------------- problem shape ----------------
#define B_      64
#define TOK     50
#define P_PER_B 49
#define NP      3136
#define NP_PAD  3200      // 25 * 128
#define D_      768
#define NM      100000
#define NM_PAD  100096    // 782 * 128
#define NTILE   782

// ---------------- GEMM tiling ------------------
#define BM 128
#define BN 128
#define KCB 128           // K elements (bytes) per chunk
#define NCHUNK 6          // 768 / 128
#define NTHR 256          // 8 warps: 2(M) x 4(N), warp tile 64x32
#define PITCH 144         // padded smem row pitch (conflict-free LDS)

// SMEM layout (dynamic)
#define SM_A0   0
#define SM_A1   18432
#define SM_B0   36864
#define SM_B1   55296
#define SM_SA   73728     // 128 f32
#define SM_C1   74240     // 128 f32
#define SM_BIAS 74752     // 128 f32
#define SM_RED  75264     // 128*4 u64 = 4096
#define SM_TOTAL (75264 + 4096)

// ---------------- scratch (device globals) -----
__device__ int8_t g_pA8[(size_t)NP_PAD * D_];    // normalized patches, int8
__device__ int8_t g_mbB8[(size_t)NM_PAD * D_];   // raw memory bank, int8
__device__ float  g_pN[(size_t)NP * D_];         // normalized patches, fp32 (rescore)
__device__ float  g_sa[NP_PAD];                  // per-patch quant scale
__device__ float  g_c1[NM_PAD];                  // sb * inv_m
__device__ float  g_inv[NM_PAD];                 // 1/(||m||+eps)
__device__ float  g_bias[NM_PAD];                // 0.5*||m_norm||^2 (1e30 pad)
__device__ float  g_p2[NP];
__device__ unsigned long long g_tile[(size_t)NP_PAD * NTILE];
__device__ int    g_maxv[NP];

// ---------------- helpers ----------------------
__device__ __forceinline__ int f2ord(float f) {
    int i = __float_as_int(f);
    return (i >= 0) ? i : (i ^ 0x7FFFFFFF);
}
__device__ __forceinline__ float ord2f(int i) {
    return __int_as_float((i >= 0) ? i : (i ^ 0x7FFFFFFF));
}
// monotone unsigned key
__device__ __forceinline__ uint32_t enc(float v) { return (uint32_t)f2ord(v) ^ 0x80000000u; }
__device__ __forceinline__ float dec(uint32_t k) { return ord2f((int)(k ^ 0x80000000u)); }

__device__ __forceinline__ uint32_t smem_u32(const void* p) {
    uint32_t a;
    asm("{ .reg .u64 t; cvta.to.shared.u64 t, %1; cvt.u32.u64 %0, t; }" : "=r"(a) : "l"(p));
    return a;
}
__device__ __forceinline__ void cp_async16(uint32_t dst, const void* src) {
    asm volatile("cp.async.cg.shared.global [%0], [%1], 16;" :: "r"(dst), "l"(src));
}
#define CP_COMMIT() asm volatile("cp.async.commit_group;" ::: "memory")
#define CP_WAIT0()  asm volatile("cp.async.wait_group 0;" ::: "memory")
#define CP_WAIT1()  asm volatile("cp.async.wait_group 1;" ::: "memory")

__device__ __forceinline__ void imma16832(int* c, const uint32_t* a, const uint32_t* b) {
    asm volatile("mma.sync.aligned.m16n8k32.row.col.s32.s8.s8.s32 "
        "{%0,%1,%2,%3}, {%4,%5,%6,%7}, {%8,%9}, {%0,%1,%2,%3};"
        : "+r"(c[0]), "+r"(c[1]), "+r"(c[2]), "+r"(c[3])
        : "r"(a[0]), "r"(a[1]), "r"(a[2]), "r"(a[3]), "r"(b[0]), "r"(b[1]));
}
__device__ __forceinline__ int8_t q8(float v, float rq) {
    int q = __float2int_rn(v * rq);
    q = max(-127, min(127, q));
    return (int8_t)q;
}

// ---------------- kernel 1: normalize patches -> fp32 + int8 ---------------
__global__ void norm_patches_kernel(const float* __restrict__ tokens) {
    int pb = blockIdx.x, tid = threadIdx.x;
    int8_t* dst8 = g_pA8 + (size_t)pb * D_;
    if (pb >= NP) {
        dst8[tid] = 0; dst8[tid + 256] = 0; dst8[tid + 512] = 0;
        if (tid == 0) g_sa[pb] = 0.0f;
        return;
    }
    int b = pb / P_PER_B, j = pb % P_PER_B;
    const float* src = tokens + ((size_t)(b * TOK + 1 + j)) * D_;
    float v0 = src[tid], v1 = src[tid + 256], v2 = src[tid + 512];
    float s = v0 * v0 + v1 * v1 + v2 * v2;
    float a = fmaxf(fabsf(v0), fmaxf(fabsf(v1), fabsf(v2)));

    __shared__ float ws[8], wa[8];
    __shared__ float s_tot, s_amax;
    #pragma unroll
    for (int o = 16; o; o >>= 1) {
        s += __shfl_xor_sync(0xFFFFFFFFu, s, o);
        a = fmaxf(a, __shfl_xor_sync(0xFFFFFFFFu, a, o));
    }
    if ((tid & 31) == 0) { ws[tid >> 5] = s; wa[tid >> 5] = a; }
    __syncthreads();
    if (tid < 32) {
        float t = (tid < 8) ? ws[tid] : 0.0f;
        float m = (tid < 8) ? wa[tid] : 0.0f;
        #pragma unroll
        for (int o = 4; o; o >>= 1) {
            t += __shfl_xor_sync(0xFFFFFFFFu, t, o);
            m = fmaxf(m, __shfl_xor_sync(0xFFFFFFFFu, m, o));
        }
        if (tid == 0) { s_tot = t; s_amax = m; }
    }
    __syncthreads();
    float tot = s_tot;
    float inv = 1.0f / (sqrtf(tot) + 1e-12f);
    float amax_n = s_amax * inv;
    float rq = (amax_n > 0.0f) ? (127.0f / amax_n) : 0.0f;

    float* pn = g_pN + (size_t)pb * D_;
    float n0 = v0 * inv, n1 = v1 * inv, n2 = v2 * inv;
    pn[tid] = n0; pn[tid + 256] = n1; pn[tid + 512] = n2;
    dst8[tid]       = q8(n0, rq);
    dst8[tid + 256] = q8(n1, rq);
    dst8[tid + 512] = q8(n2, rq);
    if (tid == 0) {
        g_sa[pb] = amax_n / 127.0f;
        g_p2[pb] = tot * inv * inv;
    }
}

// ---------------- kernel 2: MB stats + int8 quantize ------------------------
__global__ void mb_convert_kernel(const float* __restrict__ mb) {
    int row  = blockIdx.x * 8 + (threadIdx.x >> 5);
    int lane = threadIdx.x & 31;
    if (row >= NM_PAD) return;
    uint32_t* dst = (uint32_t*)(g_mbB8 + (size_t)row * D_);   // 192 u32
    if (row < NM) {
        const float4* r = (const float4*)(mb + (size_t)row * D_);
        float4 v[6]; float s = 0.0f, a = 0.0f;
        #pragma unroll
        for (int i = 0; i < 6; i++) {
            v[i] = r[lane + i * 32];
            s += v[i].x * v[i].x + v[i].y * v[i].y + v[i].z * v[i].z + v[i].w * v[i].w;
            a = fmaxf(a, fmaxf(fmaxf(fabsf(v[i].x), fabsf(v[i].y)),
                               fmaxf(fabsf(v[i].z), fabsf(v[i].w))));
        }
        #pragma unroll
        for (int o = 16; o; o >>= 1) {
            s += __shfl_xor_sync(0xFFFFFFFFu, s, o);
            a = fmaxf(a, __shfl_xor_sync(0xFFFFFFFFu, a, o));
        }
        float rq = (a > 0.0f) ? (127.0f / a) : 0.0f;
        #pragma unroll
        for (int i = 0; i < 6; i++) {
            uint32_t w = ((uint32_t)(uint8_t)q8(v[i].x, rq))
                       | ((uint32_t)(uint8_t)q8(v[i].y, rq) << 8)
                       | ((uint32_t)(uint8_t)q8(v[i].z, rq) << 16)
                       | ((uint32_t)(uint8_t)q8(v[i].w, rq) << 24);
            dst[lane + i * 32] = w;
        }
        if (lane == 0) {
            float inv = 1.0f / (sqrtf(s) + 1e-12f);
            g_inv[row]  = inv;
            g_bias[row] = 0.5f * s * inv * inv;
            g_c1[row]   = (a / 127.0f) * inv;
        }
    } else {
        #pragma unroll
        for (int i = 0; i < 6; i++) dst[lane + i * 32] = 0u;
        if (lane == 0) { g_inv[row] = 0.0f; g_bias[row] = 1e30f; g_c1[row] = 0.0f; }
    }
}

// ---------------- kernel 3: IMMA GEMM + per-tile argmax ---------------------
__global__ void __launch_bounds__(NTHR, 2)
gemm_imma_kernel() {
    extern __shared__ __align__(1024) char smem[];
    const uint32_t sbase = smem_u32(smem);
    const int tid  = threadIdx.x;
    const int wid  = tid >> 5;
    const int lane = tid & 31;
    const int p0 = blockIdx.x * BM;        // ptile fastest -> B-tile L2 reuse
    const int n0 = blockIdx.y * BN;
    const int wm = (wid & 1) * 64;
    const int wn_idx = wid >> 1;
    const int wn = wn_idx * 32;
    const int g  = lane >> 2;
    const int tq = lane & 3;

    float* sa_s   = (float*)(smem + SM_SA);
    float* c1_s   = (float*)(smem + SM_C1);
    float* bias_s = (float*)(smem + SM_BIAS);
    unsigned long long* red = (unsigned long long*)(smem + SM_RED);

    if (tid < 128) {
        sa_s[tid]   = g_sa[p0 + tid];
        c1_s[tid]   = g_c1[n0 + tid];
        bias_s[tid] = g_bias[n0 + tid];
    }

    const int8_t* gA = g_pA8  + (size_t)p0 * D_;
    const int8_t* gB = g_mbB8 + (size_t)n0 * D_;

    const int ld_row = tid >> 1;           // 0..127 (x... no: see below)
    // tile = 128 rows x 128 B = 1024 granules of 16B; 256 thr x 4 iters
    #pragma unroll
    for (int it = 0; it < 4; it++) {
        int idx = tid + it * NTHR;
        int row = idx >> 3, c = idx & 7;
        cp_async16(sbase + SM_A0 + row * PITCH + c * 16, gA + (size_t)row * D_ + c * 16);
        cp_async16(sbase + SM_B0 + row * PITCH + c * 16, gB + (size_t)row * D_ + c * 16);
    }
    CP_COMMIT();

    int acc[4][4][4];
    #pragma unroll
    for (int i = 0; i < 4; i++)
        #pragma unroll
        for (int j = 0; j < 4; j++)
            #pragma unroll
            for (int q = 0; q < 4; q++) acc[i][j][q] = 0;

    #pragma unroll 1
    for (int kc = 0; kc < NCHUNK; kc++) {
        const int s = kc & 1;
        const char* sAp = smem + (s ? SM_A1 : SM_A0);
        const char* sBp = smem + (s ? SM_B1 : SM_B0);

        if (kc + 1 < NCHUNK) {
            const uint32_t dA = sbase + (s ? SM_A0 : SM_A1);
            const uint32_t dB = sbase + (s ? SM_B0 : SM_B1);
            const int8_t* cA = gA + (size_t)(kc + 1) * KCB;
            const int8_t* cB = gB + (size_t)(kc + 1) * KCB;
            #pragma unroll
            for (int it = 0; it < 4; it++) {
                int idx = tid + it * NTHR;
                int row = idx >> 3, c = idx & 7;
                cp_async16(dA + row * PITCH + c * 16, cA + (size_t)row * D_ + c * 16);
                cp_async16(dB + row * PITCH + c * 16, cB + (size_t)row * D_ + c * 16);
            }
            CP_COMMIT();
            CP_WAIT1();
        } else {
            CP_WAIT0();
        }
        __syncthreads();

        #pragma unroll
        for (int ks = 0; ks < 4; ks++) {
            const int kb = ks * 32;
            uint32_t a[4][4], b[4][2];
            #pragma unroll
            for (int tm = 0; tm < 4; tm++) {
                const char* pa = sAp + (wm + tm * 16 + g) * PITCH + kb + tq * 4;
                a[tm][0] = *(const uint32_t*)(pa);
                a[tm][1] = *(const uint32_t*)(pa + 8 * PITCH);
                a[tm][2] = *(const uint32_t*)(pa + 16);
                a[tm][3] = *(const uint32_t*)(pa + 8 * PITCH + 16);
            }
            #pragma unroll
            for (int tn = 0; tn < 4; tn++) {
                const char* pb = sBp + (wn + tn * 8 + g) * PITCH + kb + tq * 4;
                b[tn][0] = *(const uint32_t*)(pb);
                b[tn][1] = *(const uint32_t*)(pb + 16);
            }
            #pragma unroll
            for (int tm = 0; tm < 4; tm++)
                #pragma unroll
                for (int tn = 0; tn < 4; tn++)
                    imma16832(acc[tm][tn], a[tm], b[tn]);
        }
        __syncthreads();
    }

    // ---- epilogue: v = acc*sa*c1 - bias; per-row (max, argcol) as packed u64
    #pragma unroll
    for (int tm = 0; tm < 4; tm++) {
        #pragma unroll
        for (int half = 0; half < 2; half++) {
            int rl = wm + tm * 16 + g + half * 8;
            float sar = sa_s[rl];
            unsigned long long best = 0ull;
            #pragma unroll
            for (int tn = 0; tn < 4; tn++) {
                int cl = wn + tn * 8 + tq * 2;
                float v0 = (float)acc[tm][tn][half * 2 + 0] * (sar * c1_s[cl])     - bias_s[cl];
                float v1 = (float)acc[tm][tn][half * 2 + 1] * (sar * c1_s[cl + 1]) - bias_s[cl + 1];
                unsigned long long k0 = ((unsigned long long)enc(v0) << 32) | (uint32_t)(n0 + cl);
                unsigned long long k1 = ((unsigned long long)enc(v1) << 32) | (uint32_t)(n0 + cl + 1);
                if (k0 > best) best = k0;
                if (k1 > best) best = k1;
            }
            unsigned long long o1 = __shfl_xor_sync(0xFFFFFFFFu, best, 1);
            if (o1 > best) best = o1;
            unsigned long long o2 = __shfl_xor_sync(0xFFFFFFFFu, best, 2);
            if (o2 > best) best = o2;
            if (tq == 0) red[rl * 4 + wn_idx] = best;
        }
    }
    __syncthreads();

    if (tid < BM) {
        unsigned long long m = red[tid * 4];
        #pragma unroll
        for (int j = 1; j < 4; j++)
            if (red[tid * 4 + j] > m) m = red[tid * 4 + j];
        g_tile[(size_t)(p0 + tid) * NTILE + blockIdx.y] = m;
    }
}

// ---------------- kernel 4: rescore candidates exactly ----------------------
#define MARGIN 0.01f
__global__ void rescore_kernel(const float* __restrict__ mb) {
    __shared__ int s_tiles[8][64];
    __shared__ int s_cols[8][32];
    __shared__ int s_tcnt[8], s_ccnt[8];
    const int wl = threadIdx.x >> 5;
    const int lane = threadIdx.x & 31;
    const int p = blockIdx.x * 8 + wl;
    if (p >= NP) return;

    const unsigned long long* row = g_tile + (size_t)p * NTILE;
    unsigned long long best = 0ull;
    for (int t = lane; t < NTILE; t += 32) {
        unsigned long long v = row[t];
        if (v > best) best = v;
    }
    #pragma unroll
    for (int o = 16; o; o >>= 1) {
        unsigned long long v = __shfl_xor_sync(0xFFFFFFFFu, best, o);
        if (v > best) best = v;
    }
    float bestv = dec((uint32_t)(best >> 32));
    float thr = bestv - MARGIN;
    uint32_t thrkey = enc(thr);

    if (lane == 0) { s_tcnt[wl] = 0; s_ccnt[wl] = 0; }
    __syncwarp();
    for (int t = lane; t < NTILE; t += 32) {
        if ((uint32_t)(row[t] >> 32) >= thrkey) {
            int ix = atomicAdd(&s_tcnt[wl], 1);
            if (ix < 64) s_tiles[wl][ix] = t;
        }
    }
    __syncwarp();
    int nt = min(s_tcnt[wl], 64);

    const float sa = g_sa[p];
    const int* pa = (const int*)(g_pA8 + (size_t)p * D_);   // 192 words

    for (int it = 0; it < nt; it++) {
        int t = s_tiles[wl][it];
        int colb = t * 128 + lane * 4;
        const int* b0 = (const int*)(g_mbB8 + (size_t)(colb + 0) * D_);
        const int* b1 = (const int*)(g_mbB8 + (size_t)(colb + 1) * D_);
        const int* b2 = (const int*)(g_mbB8 + (size_t)(colb + 2) * D_);
        const int* b3 = (const int*)(g_mbB8 + (size_t)(colb + 3) * D_);
        int a0 = 0, a1 = 0, a2 = 0, a3 = 0;
        #pragma unroll 4
        for (int k = 0; k < 192; k++) {
            int av = pa[k];
            a0 = __dp4a(av, b0[k], a0);
            a1 = __dp4a(av, b1[k], a1);
            a2 = __dp4a(av, b2[k], a2);
            a3 = __dp4a(av, b3[k], a3);
        }
        int accv[4] = {a0, a1, a2, a3};
        #pragma unroll
        for (int cc = 0; cc < 4; cc++) {
            int col = colb + cc;
            float vq = (float)accv[cc] * sa * g_c1[col] - g_bias[col];
            if (vq >= thr) {
                int ix = atomicAdd(&s_ccnt[wl], 1);
                if (ix < 32) s_cols[wl][ix] = col;
            }
        }
    }
    __syncwarp();
    int nc = min(s_ccnt[wl], 32);

    const float* pn = g_pN + (size_t)p * D_;
    float bestE = -3.0e38f;
    for (int ic = 0; ic < nc; ic++) {
        int col = s_cols[wl][ic];
        const float* mcol = mb + (size_t)col * D_;
        float dot = 0.0f;
        for (int k = lane; k < D_; k += 32) dot += pn[k] * mcol[k];
        #pragma unroll
        for (int o = 16; o; o >>= 1) dot += __shfl_xor_sync(0xFFFFFFFFu, dot, o);
        float v = dot * g_inv[col] - g_bias[col];
        bestE = fmaxf(bestE, v);
    }
    if (lane == 0) g_maxv[p] = f2ord(bestE);
}

// ---------------- kernel 5: finalize per-image score ------------------------
__global__ void finalize_kernel(float* __restrict__ out) {
    int b = threadIdx.x;
    if (b >= B_) return;
    float mx = -3.0e38f;
    #pragma unroll 7
    for (int j = 0; j < P_PER_B; j++) {
        int p = b * P_PER_B + j;
        float v  = ord2f(g_maxv[p]);
        float d2 = g_p2[p] - 2.0f * v;
        mx = fmaxf(mx, d2);
    }
    out[b] = sqrtf(fmaxf(mx, 1e-12f));
}

// ---------------- launch -----------------------------------------------------
extern "C" void kernel_launch(void* const* d_in, const int* in_sizes, int n_in,
                              void* d_out, int out_size) {
    (void)in_sizes; (void)n_in; (void)out_size;
    const float* tokens = (const float*)d_in[0];
    const float* mb     = (const float*)d_in[1];
    float* out          = (float*)d_out;

    norm_patches_kernel<<<NP_PAD, 256>>>(tokens);
    mb_convert_kernel<<<NM_PAD / 8, 256>>>(mb);

    cudaFuncSetAttribute(gemm_imma_kernel,
                         cudaFuncAttributeMaxDynamicSharedMemorySize, SM_TOTAL);
    dim3 grid(NP_PAD / BM, NM_PAD / BN);   // (25, 782)
    gemm_imma_kernel<<<grid, NTHR, SM_TOTAL>>>();

    rescore_kernel<<<(NP + 7) / 8, 256>>>(mb);
    finalize_kernel<<<1, 64>>>(out);
}

// round 6
// speedup vs baseline: 2.4552x; 2.4552x over previous
#include <cuda_runtime.h>
#include <math.h>
#include <limits.h>
#include <stdint.h>

// ---------------- problem shape ----------------
#define B_      64
#define TOK     50
#define P_PER_B 49
#define NP      3136
#define NP_PAD  3200      // 25 * 128
#define D_      768
#define NM      100000
#define NM_PAD  100096    // 782 * 128
#define NTILE   782

// ---------------- GEMM tiling ------------------
#define BM 128
#define BN 128
#define KCB 128           // K bytes per chunk
#define NCHUNK 6
#define NTHR 256          // 8 warps: 2(M) x 4(N), warp tile 64x32
#define PITCH 144

// SMEM layout (dynamic)
#define SM_A0   0
#define SM_A1   18432
#define SM_B0   36864
#define SM_B1   55296
#define SM_SA   73728     // 128 f32
#define SM_C1   74240
#define SM_BIAS 74752
#define SM_RED  75264     // 128*4 u64
#define SM_TOTAL (75264 + 4096)

#define MARGIN 8.0e-3f

// ---------------- scratch ----------------------
__device__ int8_t g_pA8[(size_t)NP_PAD * D_];
__device__ int8_t g_mbB8[(size_t)NM_PAD * D_];
__device__ float  g_pN[(size_t)NP * D_];
__device__ float  g_sa[NP_PAD];
__device__ float  g_c1[NM_PAD];
__device__ float  g_inv[NM_PAD];
__device__ float  g_bias[NM_PAD];
__device__ float  g_p2[NP];
__device__ unsigned long long g_tile[(size_t)NP_PAD * NTILE];
__device__ int    g_maxv[NP];

// ---------------- helpers ----------------------
__device__ __forceinline__ int f2ord(float f) {
    int i = __float_as_int(f);
    return (i >= 0) ? i : (i ^ 0x7FFFFFFF);
}
__device__ __forceinline__ float ord2f(int i) {
    return __int_as_float((i >= 0) ? i : (i ^ 0x7FFFFFFF));
}
__device__ __forceinline__ uint32_t enc(float v) { return (uint32_t)f2ord(v) ^ 0x80000000u; }
__device__ __forceinline__ float dec(uint32_t k) { return ord2f((int)(k ^ 0x80000000u)); }

__device__ __forceinline__ uint32_t smem_u32(const void* p) {
    uint32_t a;
    asm("{ .reg .u64 t; cvta.to.shared.u64 t, %1; cvt.u32.u64 %0, t; }" : "=r"(a) : "l"(p));
    return a;
}
__device__ __forceinline__ void cp_async16(uint32_t dst, const void* src) {
    asm volatile("cp.async.cg.shared.global [%0], [%1], 16;" :: "r"(dst), "l"(src));
}
#define CP_COMMIT() asm volatile("cp.async.commit_group;" ::: "memory")
#define CP_WAIT0()  asm volatile("cp.async.wait_group 0;" ::: "memory")

__device__ __forceinline__ void imma16832(int* c, const uint32_t* a, const uint32_t* b) {
    asm volatile("mma.sync.aligned.m16n8k32.row.col.s32.s8.s8.s32 "
        "{%0,%1,%2,%3}, {%4,%5,%6,%7}, {%8,%9}, {%0,%1,%2,%3};"
        : "+r"(c[0]), "+r"(c[1]), "+r"(c[2]), "+r"(c[3])
        : "r"(a[0]), "r"(a[1]), "r"(a[2]), "r"(a[3]), "r"(b[0]), "r"(b[1]));
}
__device__ __forceinline__ int8_t q8(float v, float rq) {
    int q = __float2int_rn(v * rq);
    q = max(-127, min(127, q));
    return (int8_t)q;
}

// ---------------- kernel 1: normalize patches -> fp32 + int8 ---------------
__global__ void norm_patches_kernel(const float* __restrict__ tokens) {
    int pb = blockIdx.x, tid = threadIdx.x;
    int8_t* dst8 = g_pA8 + (size_t)pb * D_;
    if (pb >= NP) {
        dst8[tid] = 0; dst8[tid + 256] = 0; dst8[tid + 512] = 0;
        if (tid == 0) g_sa[pb] = 0.0f;
        return;
    }
    int b = pb / P_PER_B, j = pb % P_PER_B;
    const float* src = tokens + ((size_t)(b * TOK + 1 + j)) * D_;
    float v0 = src[tid], v1 = src[tid + 256], v2 = src[tid + 512];
    float s = v0 * v0 + v1 * v1 + v2 * v2;
    float a = fmaxf(fabsf(v0), fmaxf(fabsf(v1), fabsf(v2)));

    __shared__ float ws[8], wa[8];
    __shared__ float s_tot, s_amax;
    #pragma unroll
    for (int o = 16; o; o >>= 1) {
        s += __shfl_xor_sync(0xFFFFFFFFu, s, o);
        a = fmaxf(a, __shfl_xor_sync(0xFFFFFFFFu, a, o));
    }
    if ((tid & 31) == 0) { ws[tid >> 5] = s; wa[tid >> 5] = a; }
    __syncthreads();
    if (tid < 32) {
        float t = (tid < 8) ? ws[tid] : 0.0f;
        float m = (tid < 8) ? wa[tid] : 0.0f;
        #pragma unroll
        for (int o = 4; o; o >>= 1) {
            t += __shfl_xor_sync(0xFFFFFFFFu, t, o);
            m = fmaxf(m, __shfl_xor_sync(0xFFFFFFFFu, m, o));
        }
        if (tid == 0) { s_tot = t; s_amax = m; }
    }
    __syncthreads();
    float tot = s_tot;
    float inv = 1.0f / (sqrtf(tot) + 1e-12f);
    float amax_n = s_amax * inv;
    float rq = (amax_n > 0.0f) ? (127.0f / amax_n) : 0.0f;

    float* pn = g_pN + (size_t)pb * D_;
    float n0 = v0 * inv, n1 = v1 * inv, n2 = v2 * inv;
    pn[tid] = n0; pn[tid + 256] = n1; pn[tid + 512] = n2;
    dst8[tid]       = q8(n0, rq);
    dst8[tid + 256] = q8(n1, rq);
    dst8[tid + 512] = q8(n2, rq);
    if (tid == 0) {
        g_sa[pb] = amax_n / 127.0f;
        g_p2[pb] = tot * inv * inv;
    }
}

// ---------------- kernel 2: MB stats + int8 quantize ------------------------
__global__ void mb_convert_kernel(const float* __restrict__ mb) {
    int row  = blockIdx.x * 8 + (threadIdx.x >> 5);
    int lane = threadIdx.x & 31;
    if (row >= NM_PAD) return;
    uint32_t* dst = (uint32_t*)(g_mbB8 + (size_t)row * D_);
    if (row < NM) {
        const float4* r = (const float4*)(mb + (size_t)row * D_);
        float4 v[6]; float s = 0.0f, a = 0.0f;
        #pragma unroll
        for (int i = 0; i < 6; i++) {
            v[i] = r[lane + i * 32];
            s += v[i].x * v[i].x + v[i].y * v[i].y + v[i].z * v[i].z + v[i].w * v[i].w;
            a = fmaxf(a, fmaxf(fmaxf(fabsf(v[i].x), fabsf(v[i].y)),
                               fmaxf(fabsf(v[i].z), fabsf(v[i].w))));
        }
        #pragma unroll
        for (int o = 16; o; o >>= 1) {
            s += __shfl_xor_sync(0xFFFFFFFFu, s, o);
            a = fmaxf(a, __shfl_xor_sync(0xFFFFFFFFu, a, o));
        }
        float rq = (a > 0.0f) ? (127.0f / a) : 0.0f;
        #pragma unroll
        for (int i = 0; i < 6; i++) {
            uint32_t w = ((uint32_t)(uint8_t)q8(v[i].x, rq))
                       | ((uint32_t)(uint8_t)q8(v[i].y, rq) << 8)
                       | ((uint32_t)(uint8_t)q8(v[i].z, rq) << 16)
                       | ((uint32_t)(uint8_t)q8(v[i].w, rq) << 24);
            dst[lane + i * 32] = w;
        }
        if (lane == 0) {
            float inv = 1.0f / (sqrtf(s) + 1e-12f);
            g_inv[row]  = inv;
            g_bias[row] = 0.5f * s * inv * inv;
            g_c1[row]   = (a / 127.0f) * inv;
        }
    } else {
        #pragma unroll
        for (int i = 0; i < 6; i++) dst[lane + i * 32] = 0u;
        if (lane == 0) { g_inv[row] = 0.0f; g_bias[row] = 1e30f; g_c1[row] = 0.0f; }
    }
}

// ---------------- kernel 3: IMMA GEMM, single-sync pipeline -----------------
__global__ void __launch_bounds__(NTHR, 2)
gemm_imma_kernel() {
    extern __shared__ __align__(1024) char smem[];
    const uint32_t sbase = smem_u32(smem);
    const int tid  = threadIdx.x;
    const int wid  = tid >> 5;
    const int lane = tid & 31;
    const int p0 = blockIdx.x * BM;
    const int n0 = blockIdx.y * BN;
    const int wm = (wid & 1) * 64;
    const int wn_idx = wid >> 1;
    const int wn = wn_idx * 32;
    const int g  = lane >> 2;
    const int tq = lane & 3;

    float* sa_s   = (float*)(smem + SM_SA);
    float* c1_s   = (float*)(smem + SM_C1);
    float* bias_s = (float*)(smem + SM_BIAS);
    unsigned long long* red = (unsigned long long*)(smem + SM_RED);

    if (tid < 128) {
        sa_s[tid]   = g_sa[p0 + tid];
        c1_s[tid]   = g_c1[n0 + tid];
        bias_s[tid] = g_bias[n0 + tid];
    }

    const int8_t* gA = g_pA8  + (size_t)p0 * D_;
    const int8_t* gB = g_mbB8 + (size_t)n0 * D_;
    const int ld_r = tid >> 3;        // base row (x4 iters via +64)
    const int ld_c = tid & 7;

    // prologue: chunk 0 -> stage 0
    #pragma unroll
    for (int it = 0; it < 4; it++) {
        int row = ld_r + it * 32;
        cp_async16(sbase + SM_A0 + row * PITCH + ld_c * 16, gA + (size_t)row * D_ + ld_c * 16);
        cp_async16(sbase + SM_B0 + row * PITCH + ld_c * 16, gB + (size_t)row * D_ + ld_c * 16);
    }
    CP_COMMIT();

    int acc[4][4][4];
    #pragma unroll
    for (int i = 0; i < 4; i++)
        #pragma unroll
        for (int j = 0; j < 4; j++)
            #pragma unroll
            for (int q = 0; q < 4; q++) acc[i][j][q] = 0;

    #pragma unroll 1
    for (int kc = 0; kc < NCHUNK; kc++) {
        const int s = kc & 1;
        const char* sAp = smem + (s ? SM_A1 : SM_A0);
        const char* sBp = smem + (s ? SM_B1 : SM_B0);

        CP_WAIT0();
        __syncthreads();   // everyone: chunk kc ready AND done reading stage 1-s

        if (kc + 1 < NCHUNK) {
            const uint32_t dA = sbase + (s ? SM_A0 : SM_A1);
            const uint32_t dB = sbase + (s ? SM_B0 : SM_B1);
            const int8_t* cA = gA + (size_t)(kc + 1) * KCB;
            const int8_t* cB = gB + (size_t)(kc + 1) * KCB;
            #pragma unroll
            for (int it = 0; it < 4; it++) {
                int row = ld_r + it * 32;
                cp_async16(dA + row * PITCH + ld_c * 16, cA + (size_t)row * D_ + ld_c * 16);
                cp_async16(dB + row * PITCH + ld_c * 16, cB + (size_t)row * D_ + ld_c * 16);
            }
            CP_COMMIT();
        }

        #pragma unroll
        for (int ks = 0; ks < 4; ks++) {
            const int kb = ks * 32;
            uint32_t a[4][4], b[4][2];
            #pragma unroll
            for (int tm = 0; tm < 4; tm++) {
                const char* pa = sAp + (wm + tm * 16 + g) * PITCH + kb + tq * 4;
                a[tm][0] = *(const uint32_t*)(pa);
                a[tm][1] = *(const uint32_t*)(pa + 8 * PITCH);
                a[tm][2] = *(const uint32_t*)(pa + 16);
                a[tm][3] = *(const uint32_t*)(pa + 8 * PITCH + 16);
            }
            #pragma unroll
            for (int tn = 0; tn < 4; tn++) {
                const char* pb = sBp + (wn + tn * 8 + g) * PITCH + kb + tq * 4;
                b[tn][0] = *(const uint32_t*)(pb);
                b[tn][1] = *(const uint32_t*)(pb + 16);
            }
            #pragma unroll
            for (int tm = 0; tm < 4; tm++)
                #pragma unroll
                for (int tn = 0; tn < 4; tn++)
                    imma16832(acc[tm][tn], a[tm], b[tn]);
        }
    }
    __syncthreads();

    // epilogue: per-row (max,col) packed u64, per-tile store
    #pragma unroll
    for (int tm = 0; tm < 4; tm++) {
        #pragma unroll
        for (int half = 0; half < 2; half++) {
            int rl = wm + tm * 16 + g + half * 8;
            float sar = sa_s[rl];
            unsigned long long best = 0ull;
            #pragma unroll
            for (int tn = 0; tn < 4; tn++) {
                int cl = wn + tn * 8 + tq * 2;
                float v0 = (float)acc[tm][tn][half * 2 + 0] * (sar * c1_s[cl])     - bias_s[cl];
                float v1 = (float)acc[tm][tn][half * 2 + 1] * (sar * c1_s[cl + 1]) - bias_s[cl + 1];
                unsigned long long k0 = ((unsigned long long)enc(v0) << 32) | (uint32_t)(n0 + cl);
                unsigned long long k1 = ((unsigned long long)enc(v1) << 32) | (uint32_t)(n0 + cl + 1);
                if (k0 > best) best = k0;
                if (k1 > best) best = k1;
            }
            unsigned long long o1 = __shfl_xor_sync(0xFFFFFFFFu, best, 1);
            if (o1 > best) best = o1;
            unsigned long long o2 = __shfl_xor_sync(0xFFFFFFFFu, best, 2);
            if (o2 > best) best = o2;
            if (tq == 0) red[rl * 4 + wn_idx] = best;
        }
    }
    __syncthreads();

    if (tid < BM) {
        unsigned long long m = red[tid * 4];
        #pragma unroll
        for (int j = 1; j < 4; j++)
            if (red[tid * 4 + j] > m) m = red[tid * 4 + j];
        g_tile[(size_t)(p0 + tid) * NTILE + blockIdx.y] = m;
    }
}

// ---------------- kernel 4: rescore (one CTA per patch) ---------------------
__global__ void __launch_bounds__(256)
rescore_kernel(const float* __restrict__ mb) {
    __shared__ unsigned long long s_bw[8];
    __shared__ int s_tiles[128];
    __shared__ int s_cols[64];
    __shared__ int s_tcnt, s_ccnt;
    __shared__ float s_thr;
    __shared__ float s_val[64];

    const int p = blockIdx.x;
    const int tid = threadIdx.x;
    const int wid = tid >> 5;
    const int lane = tid & 31;

    // --- 1. block max over 782 tile keys (coalesced) ---
    const unsigned long long* row = g_tile + (size_t)p * NTILE;
    unsigned long long best = 0ull;
    for (int t = tid; t < NTILE; t += 256) {
        unsigned long long v = row[t];
        if (v > best) best = v;
    }
    #pragma unroll
    for (int o = 16; o; o >>= 1) {
        unsigned long long v = __shfl_xor_sync(0xFFFFFFFFu, best, o);
        if (v > best) best = v;
    }
    if (lane == 0) s_bw[wid] = best;
    if (tid == 0) { s_tcnt = 0; s_ccnt = 0; }
    __syncthreads();
    if (tid == 0) {
        unsigned long long m = s_bw[0];
        #pragma unroll
        for (int w = 1; w < 8; w++) if (s_bw[w] > m) m = s_bw[w];
        s_thr = dec((uint32_t)(m >> 32)) - MARGIN;
    }
    __syncthreads();
    const float thr = s_thr;
    const uint32_t thrkey = enc(thr);

    // --- 2. candidate tiles ---
    for (int t = tid; t < NTILE; t += 256) {
        if ((uint32_t)(row[t] >> 32) >= thrkey) {
            int ix = atomicAdd(&s_tcnt, 1);
            if (ix < 128) s_tiles[ix] = t;
        }
    }
    __syncthreads();
    const int nt = min(s_tcnt, 128);
    const int ncols = nt * 128;

    // --- 3. int8 filter, warp-cooperative, coalesced; 4 cols in flight ---
    const float sa = g_sa[p];
    int paw[6];
    {
        const int* pa = (const int*)(g_pA8 + (size_t)p * D_);
        #pragma unroll
        for (int i = 0; i < 6; i++) paw[i] = pa[lane + i * 32];
    }
    for (int base = wid * 4; base < ncols; base += 32) {
        int acc4[4] = {0, 0, 0, 0};
        int col4[4];
        #pragma unroll
        for (int j = 0; j < 4; j++) {
            int idx = base + j;
            int t = s_tiles[idx >> 7];
            col4[j] = t * 128 + (idx & 127);
            const int* bc = (const int*)(g_mbB8 + (size_t)col4[j] * D_);
            #pragma unroll
            for (int i = 0; i < 6; i++)
                acc4[j] = __dp4a(paw[i], bc[lane + i * 32], acc4[j]);
        }
        #pragma unroll
        for (int j = 0; j < 4; j++) {
            int dot = __reduce_add_sync(0xFFFFFFFFu, acc4[j]);
            if (lane == 0) {
                int col = col4[j];
                float vq = (float)dot * sa * g_c1[col] - g_bias[col];
                if (vq >= thr) {
                    int ix = atomicAdd(&s_ccnt, 1);
                    if (ix < 64) s_cols[ix] = col;
                }
            }
        }
    }
    __syncthreads();
    const int nc = min(s_ccnt, 64);

    // --- 4. exact fp32 rescore of survivors ---
    float pnw[24];
    {
        const float* pn = g_pN + (size_t)p * D_;
        #pragma unroll
        for (int i = 0; i < 24; i++) pnw[i] = pn[lane + i * 32];
    }
    for (int ic = wid; ic < nc; ic += 8) {
        int col = s_cols[ic];
        const float* mcol = mb + (size_t)col * D_;
        float dot = 0.0f;
        #pragma unroll
        for (int i = 0; i < 24; i++) dot += pnw[i] * mcol[lane + i * 32];
        #pragma unroll
        for (int o = 16; o; o >>= 1) dot += __shfl_xor_sync(0xFFFFFFFFu, dot, o);
        if (lane == 0) s_val[ic] = dot * g_inv[col] - g_bias[col];
    }
    __syncthreads();
    if (tid == 0) {
        float bestE = -3.0e38f;
        for (int ic = 0; ic < nc; ic++) bestE = fmaxf(bestE, s_val[ic]);
        g_maxv[p] = f2ord(bestE);
    }
}

// ---------------- kernel 5: finalize ----------------------------------------
__global__ void finalize_kernel(float* __restrict__ out) {
    int b = threadIdx.x;
    if (b >= B_) return;
    float mx = -3.0e38f;
    #pragma unroll 7
    for (int j = 0; j < P_PER_B; j++) {
        int p = b * P_PER_B + j;
        float v  = ord2f(g_maxv[p]);
        float d2 = g_p2[p] - 2.0f * v;
        mx = fmaxf(mx, d2);
    }
    out[b] = sqrtf(fmaxf(mx, 1e-12f));
}

// ---------------- launch -----------------------------------------------------
extern "C" void kernel_launch(void* const* d_in, const int* in_sizes, int n_in,
                              void* d_out, int out_size) {
    (void)in_sizes; (void)n_in; (void)out_size;
    const float* tokens = (const float*)d_in[0];
    const float* mb     = (const float*)d_in[1];
    float* out          = (float*)d_out;

    norm_patches_kernel<<<NP_PAD, 256>>>(tokens);
    mb_convert_kernel<<<NM_PAD / 8, 256>>>(mb);

    cudaFuncSetAttribute(gemm_imma_kernel,
                         cudaFuncAttributeMaxDynamicSharedMemorySize, SM_TOTAL);
    dim3 grid(NP_PAD / BM, NM_PAD / BN);   // (25, 782)
    gemm_imma_kernel<<<grid, NTHR, SM_TOTAL>>>();

    rescore_kernel<<<NP, 256>>>(mb);
    finalize_kernel<<<1, 64>>>(out);
}

// round 7
// speedup vs baseline: 2.8907x; 1.1774x over previous
#include <cuda_runtime.h>
#include <math.h>
#include <limits.h>
#include <stdint.h>

// ---------------- problem shape ----------------
#define B_      64
#define TOK     50
#define P_PER_B 49
#define NP      3136
#define NP_PAD  3200      // 25 * 128
#define D_      768
#define NM      100000
#define NM_PAD  100096    // 782 * 128
#define NTILE   782

// ---------------- GEMM tiling ------------------
#define BM 128
#define BN 128
#define KCB 128           // K bytes per chunk (= 128B rows, SW128 atom)
#define NCHUNK 6
#define NTHR 256          // 8 warps: 2(M) x 4(N), warp tile 64x32

// SMEM layout (dynamic); tiles are 128 rows x 128 B = 16 KB
#define SM_A0   0
#define SM_A1   16384
#define SM_B0   32768
#define SM_B1   49152
#define SM_SA   65536     // 128 f32
#define SM_C1   66048
#define SM_BIAS 66560
#define SM_RED  67072     // 128*4 u64 = 4096
#define SM_TOTAL (67072 + 4096)

#define MARGIN 8.0e-3f

// ---------------- scratch ----------------------
__device__ int8_t g_pA8[(size_t)NP_PAD * D_];
__device__ int8_t g_mbB8[(size_t)NM_PAD * D_];
__device__ float  g_pN[(size_t)NP * D_];
__device__ float  g_sa[NP_PAD];
__device__ float  g_c1[NM_PAD];
__device__ float  g_inv[NM_PAD];
__device__ float  g_bias[NM_PAD];
__device__ float  g_p2[NP];
__device__ unsigned long long g_tile[(size_t)NP_PAD * NTILE];
__device__ int    g_maxv[NP];

// ---------------- helpers ----------------------
__device__ __forceinline__ int f2ord(float f) {
    int i = __float_as_int(f);
    return (i >= 0) ? i : (i ^ 0x7FFFFFFF);
}
__device__ __forceinline__ float ord2f(int i) {
    return __int_as_float((i >= 0) ? i : (i ^ 0x7FFFFFFF));
}
__device__ __forceinline__ uint32_t enc(float v) { return (uint32_t)f2ord(v) ^ 0x80000000u; }
__device__ __forceinline__ float dec(uint32_t k) { return ord2f((int)(k ^ 0x80000000u)); }

__device__ __forceinline__ uint32_t smem_u32(const void* p) {
    uint32_t a;
    asm("{ .reg .u64 t; cvta.to.shared.u64 t, %1; cvt.u32.u64 %0, t; }" : "=r"(a) : "l"(p));
    return a;
}
__device__ __forceinline__ void cp_async16(uint32_t dst, const void* src) {
    asm volatile("cp.async.cg.shared.global [%0], [%1], 16;" :: "r"(dst), "l"(src));
}
#define CP_COMMIT() asm volatile("cp.async.commit_group;" ::: "memory")
#define CP_WAIT0()  asm volatile("cp.async.wait_group 0;" ::: "memory")

__device__ __forceinline__ uint32_t sw128(uint32_t off) {
    return off ^ ((off >> 3) & 0x70);
}
__device__ __forceinline__ void ldmat_x4(uint32_t* r, uint32_t addr) {
    asm volatile("ldmatrix.sync.aligned.m8n8.x4.shared.b16 {%0,%1,%2,%3}, [%4];"
        : "=r"(r[0]), "=r"(r[1]), "=r"(r[2]), "=r"(r[3]) : "r"(addr));
}
__device__ __forceinline__ void imma16832(int* c, const uint32_t* a, const uint32_t* b) {
    asm volatile("mma.sync.aligned.m16n8k32.row.col.s32.s8.s8.s32 "
        "{%0,%1,%2,%3}, {%4,%5,%6,%7}, {%8,%9}, {%0,%1,%2,%3};"
        : "+r"(c[0]), "+r"(c[1]), "+r"(c[2]), "+r"(c[3])
        : "r"(a[0]), "r"(a[1]), "r"(a[2]), "r"(a[3]), "r"(b[0]), "r"(b[1]));
}
__device__ __forceinline__ int8_t q8(float v, float rq) {
    int q = __float2int_rn(v * rq);
    q = max(-127, min(127, q));
    return (int8_t)q;
}

// ---------------- kernel 1: normalize patches -> fp32 + int8 ---------------
__global__ void norm_patches_kernel(const float* __restrict__ tokens) {
    int pb = blockIdx.x, tid = threadIdx.x;
    int8_t* dst8 = g_pA8 + (size_t)pb * D_;
    if (pb >= NP) {
        dst8[tid] = 0; dst8[tid + 256] = 0; dst8[tid + 512] = 0;
        if (tid == 0) g_sa[pb] = 0.0f;
        return;
    }
    int b = pb / P_PER_B, j = pb % P_PER_B;
    const float* src = tokens + ((size_t)(b * TOK + 1 + j)) * D_;
    float v0 = src[tid], v1 = src[tid + 256], v2 = src[tid + 512];
    float s = v0 * v0 + v1 * v1 + v2 * v2;
    float a = fmaxf(fabsf(v0), fmaxf(fabsf(v1), fabsf(v2)));

    __shared__ float ws[8], wa[8];
    __shared__ float s_tot, s_amax;
    #pragma unroll
    for (int o = 16; o; o >>= 1) {
        s += __shfl_xor_sync(0xFFFFFFFFu, s, o);
        a = fmaxf(a, __shfl_xor_sync(0xFFFFFFFFu, a, o));
    }
    if ((tid & 31) == 0) { ws[tid >> 5] = s; wa[tid >> 5] = a; }
    __syncthreads();
    if (tid < 32) {
        float t = (tid < 8) ? ws[tid] : 0.0f;
        float m = (tid < 8) ? wa[tid] : 0.0f;
        #pragma unroll
        for (int o = 4; o; o >>= 1) {
            t += __shfl_xor_sync(0xFFFFFFFFu, t, o);
            m = fmaxf(m, __shfl_xor_sync(0xFFFFFFFFu, m, o));
        }
        if (tid == 0) { s_tot = t; s_amax = m; }
    }
    __syncthreads();
    float tot = s_tot;
    float inv = 1.0f / (sqrtf(tot) + 1e-12f);
    float amax_n = s_amax * inv;
    float rq = (amax_n > 0.0f) ? (127.0f / amax_n) : 0.0f;

    float* pn = g_pN + (size_t)pb * D_;
    float n0 = v0 * inv, n1 = v1 * inv, n2 = v2 * inv;
    pn[tid] = n0; pn[tid + 256] = n1; pn[tid + 512] = n2;
    dst8[tid]       = q8(n0, rq);
    dst8[tid + 256] = q8(n1, rq);
    dst8[tid + 512] = q8(n2, rq);
    if (tid == 0) {
        g_sa[pb] = amax_n / 127.0f;
        g_p2[pb] = tot * inv * inv;
    }
}

// ---------------- kernel 2: MB stats + int8 quantize ------------------------
__global__ void mb_convert_kernel(const float* __restrict__ mb) {
    int row  = blockIdx.x * 8 + (threadIdx.x >> 5);
    int lane = threadIdx.x & 31;
    if (row >= NM_PAD) return;
    uint32_t* dst = (uint32_t*)(g_mbB8 + (size_t)row * D_);
    if (row < NM) {
        const float4* r = (const float4*)(mb + (size_t)row * D_);
        float4 v[6]; float s = 0.0f, a = 0.0f;
        #pragma unroll
        for (int i = 0; i < 6; i++) {
            v[i] = r[lane + i * 32];
            s += v[i].x * v[i].x + v[i].y * v[i].y + v[i].z * v[i].z + v[i].w * v[i].w;
            a = fmaxf(a, fmaxf(fmaxf(fabsf(v[i].x), fabsf(v[i].y)),
                               fmaxf(fabsf(v[i].z), fabsf(v[i].w))));
        }
        #pragma unroll
        for (int o = 16; o; o >>= 1) {
            s += __shfl_xor_sync(0xFFFFFFFFu, s, o);
            a = fmaxf(a, __shfl_xor_sync(0xFFFFFFFFu, a, o));
        }
        float rq = (a > 0.0f) ? (127.0f / a) : 0.0f;
        #pragma unroll
        for (int i = 0; i < 6; i++) {
            uint32_t w = ((uint32_t)(uint8_t)q8(v[i].x, rq))
                       | ((uint32_t)(uint8_t)q8(v[i].y, rq) << 8)
                       | ((uint32_t)(uint8_t)q8(v[i].z, rq) << 16)
                       | ((uint32_t)(uint8_t)q8(v[i].w, rq) << 24);
            dst[lane + i * 32] = w;
        }
        if (lane == 0) {
            float inv = 1.0f / (sqrtf(s) + 1e-12f);
            g_inv[row]  = inv;
            g_bias[row] = 0.5f * s * inv * inv;
            g_c1[row]   = (a / 127.0f) * inv;
        }
    } else {
        #pragma unroll
        for (int i = 0; i < 6; i++) dst[lane + i * 32] = 0u;
        if (lane == 0) { g_inv[row] = 0.0f; g_bias[row] = 1e30f; g_c1[row] = 0.0f; }
    }
}

// ---------------- kernel 3: IMMA GEMM (ldmatrix, single-sync) ---------------
__global__ void __launch_bounds__(NTHR, 2)
gemm_imma_kernel() {
    extern __shared__ __align__(1024) char smem[];
    const uint32_t sbase = smem_u32(smem);
    const int tid  = threadIdx.x;
    const int wid  = tid >> 5;
    const int lane = tid & 31;
    const int p0 = blockIdx.x * BM;
    const int n0 = blockIdx.y * BN;
    const int wm = (wid & 1) * 64;
    const int wn_idx = wid >> 1;
    const int wn = wn_idx * 32;
    const int g  = lane >> 2;
    const int tq = lane & 3;

    float* sa_s   = (float*)(smem + SM_SA);
    float* c1_s   = (float*)(smem + SM_C1);
    float* bias_s = (float*)(smem + SM_BIAS);
    unsigned long long* red = (unsigned long long*)(smem + SM_RED);

    if (tid < 128) {
        sa_s[tid]   = g_sa[p0 + tid];
        c1_s[tid]   = g_c1[n0 + tid];
        bias_s[tid] = g_bias[n0 + tid];
    }

    const int8_t* gA = g_pA8  + (size_t)p0 * D_;
    const int8_t* gB = g_mbB8 + (size_t)n0 * D_;
    const int ld_r = tid >> 3;        // base row, +32 per iter
    const int ld_c = tid & 7;         // 16B granule in 128B row

    // prologue: chunk 0 -> stage 0 (SW128-swizzled stores)
    #pragma unroll
    for (int it = 0; it < 4; it++) {
        int row = ld_r + it * 32;
        uint32_t off = sw128((uint32_t)(row * 128 + ld_c * 16));
        cp_async16(sbase + SM_A0 + off, gA + (size_t)row * D_ + ld_c * 16);
        cp_async16(sbase + SM_B0 + off, gB + (size_t)row * D_ + ld_c * 16);
    }
    CP_COMMIT();

    // ldmatrix lane-address components (same geometry as bf16 m16n8k16)
    const uint32_t aRow = (uint32_t)(wm + (lane & 15)) * 128;
    const uint32_t aCol = (uint32_t)((lane >> 4) << 4);
    const uint32_t bRow = (uint32_t)(wn + (lane & 7) + ((lane >> 4) << 3)) * 128;
    const uint32_t bCol = (uint32_t)(((lane >> 3) & 1) << 4);

    int acc[4][4][4];
    #pragma unroll
    for (int i = 0; i < 4; i++)
        #pragma unroll
        for (int j = 0; j < 4; j++)
            #pragma unroll
            for (int q = 0; q < 4; q++) acc[i][j][q] = 0;

    #pragma unroll 1
    for (int kc = 0; kc < NCHUNK; kc++) {
        const int s = kc & 1;
        const uint32_t sA = sbase + (s ? SM_A1 : SM_A0);
        const uint32_t sB = sbase + (s ? SM_B1 : SM_B0);

        CP_WAIT0();
        __syncthreads();   // chunk kc landed AND all warps done reading other stage

        if (kc + 1 < NCHUNK) {
            const uint32_t dA = sbase + (s ? SM_A0 : SM_A1);
            const uint32_t dB = sbase + (s ? SM_B0 : SM_B1);
            const int8_t* cA = gA + (size_t)(kc + 1) * KCB;
            const int8_t* cB = gB + (size_t)(kc + 1) * KCB;
            #pragma unroll
            for (int it = 0; it < 4; it++) {
                int row = ld_r + it * 32;
                uint32_t off = sw128((uint32_t)(row * 128 + ld_c * 16));
                cp_async16(dA + off, cA + (size_t)row * D_ + ld_c * 16);
                cp_async16(dB + off, cB + (size_t)row * D_ + ld_c * 16);
            }
            CP_COMMIT();
        }

        #pragma unroll
        for (int ks = 0; ks < 4; ks++) {
            const uint32_t kb = (uint32_t)(ks * 32);
            uint32_t af[4][4], bf[2][4];
            #pragma unroll
            for (int tm = 0; tm < 4; tm++)
                ldmat_x4(af[tm], sA + sw128(aRow + (uint32_t)(tm * 16 * 128) + kb + aCol));
            #pragma unroll
            for (int bn = 0; bn < 2; bn++)
                ldmat_x4(bf[bn], sB + sw128(bRow + (uint32_t)(bn * 16 * 128) + kb + bCol));
            #pragma unroll
            for (int tm = 0; tm < 4; tm++)
                #pragma unroll
                for (int tn = 0; tn < 4; tn++)
                    imma16832(acc[tm][tn], af[tm], bf[tn >> 1] + (tn & 1) * 2);
        }
    }
    __syncthreads();

    // epilogue: per-row (max,col) packed u64, per-tile store
    #pragma unroll
    for (int tm = 0; tm < 4; tm++) {
        #pragma unroll
        for (int half = 0; half < 2; half++) {
            int rl = wm + tm * 16 + g + half * 8;
            float sar = sa_s[rl];
            unsigned long long best = 0ull;
            #pragma unroll
            for (int tn = 0; tn < 4; tn++) {
                int cl = wn + tn * 8 + tq * 2;
                float v0 = (float)acc[tm][tn][half * 2 + 0] * (sar * c1_s[cl])     - bias_s[cl];
                float v1 = (float)acc[tm][tn][half * 2 + 1] * (sar * c1_s[cl + 1]) - bias_s[cl + 1];
                unsigned long long k0 = ((unsigned long long)enc(v0) << 32) | (uint32_t)(n0 + cl);
                unsigned long long k1 = ((unsigned long long)enc(v1) << 32) | (uint32_t)(n0 + cl + 1);
                if (k0 > best) best = k0;
                if (k1 > best) best = k1;
            }
            unsigned long long o1 = __shfl_xor_sync(0xFFFFFFFFu, best, 1);
            if (o1 > best) best = o1;
            unsigned long long o2 = __shfl_xor_sync(0xFFFFFFFFu, best, 2);
            if (o2 > best) best = o2;
            if (tq == 0) red[rl * 4 + wn_idx] = best;
        }
    }
    __syncthreads();

    if (tid < BM) {
        unsigned long long m = red[tid * 4];
        #pragma unroll
        for (int j = 1; j < 4; j++)
            if (red[tid * 4 + j] > m) m = red[tid * 4 + j];
        g_tile[(size_t)(p0 + tid) * NTILE + blockIdx.y] = m;
    }
}

// ---------------- kernel 4: rescore (one CTA per patch) ---------------------
__global__ void __launch_bounds__(256)
rescore_kernel(const float* __restrict__ mb) {
    __shared__ unsigned long long s_bw[8];
    __shared__ int s_tiles[128];
    __shared__ int s_cols[64];
    __shared__ int s_tcnt, s_ccnt;
    __shared__ float s_thr;
    __shared__ float s_val[64];

    const int p = blockIdx.x;
    const int tid = threadIdx.x;
    const int wid = tid >> 5;
    const int lane = tid & 31;

    const unsigned long long* row = g_tile + (size_t)p * NTILE;
    unsigned long long best = 0ull;
    for (int t = tid; t < NTILE; t += 256) {
        unsigned long long v = row[t];
        if (v > best) best = v;
    }
    #pragma unroll
    for (int o = 16; o; o >>= 1) {
        unsigned long long v = __shfl_xor_sync(0xFFFFFFFFu, best, o);
        if (v > best) best = v;
    }
    if (lane == 0) s_bw[wid] = best;
    if (tid == 0) { s_tcnt = 0; s_ccnt = 0; }
    __syncthreads();
    if (tid == 0) {
        unsigned long long m = s_bw[0];
        #pragma unroll
        for (int w = 1; w < 8; w++) if (s_bw[w] > m) m = s_bw[w];
        s_thr = dec((uint32_t)(m >> 32)) - MARGIN;
    }
    __syncthreads();
    const float thr = s_thr;
    const uint32_t thrkey = enc(thr);

    for (int t = tid; t < NTILE; t += 256) {
        if ((uint32_t)(row[t] >> 32) >= thrkey) {
            int ix = atomicAdd(&s_tcnt, 1);
            if (ix < 128) s_tiles[ix] = t;
        }
    }
    __syncthreads();
    const int nt = min(s_tcnt, 128);
    const int ncols = nt * 128;

    const float sa = g_sa[p];
    int paw[6];
    {
        const int* pa = (const int*)(g_pA8 + (size_t)p * D_);
        #pragma unroll
        for (int i = 0; i < 6; i++) paw[i] = pa[lane + i * 32];
    }
    for (int base = wid * 4; base < ncols; base += 32) {
        int acc4[4] = {0, 0, 0, 0};
        int col4[4];
        #pragma unroll
        for (int j = 0; j < 4; j++) {
            int idx = base + j;
            int t = s_tiles[idx >> 7];
            col4[j] = t * 128 + (idx & 127);
            const int* bc = (const int*)(g_mbB8 + (size_t)col4[j] * D_);
            #pragma unroll
            for (int i = 0; i < 6; i++)
                acc4[j] = __dp4a(paw[i], bc[lane + i * 32], acc4[j]);
        }
        #pragma unroll
        for (int j = 0; j < 4; j++) {
            int dot = __reduce_add_sync(0xFFFFFFFFu, acc4[j]);
            if (lane == 0) {
                int col = col4[j];
                float vq = (float)dot * sa * g_c1[col] - g_bias[col];
                if (vq >= thr) {
                    int ix = atomicAdd(&s_ccnt, 1);
                    if (ix < 64) s_cols[ix] = col;
                }
            }
        }
    }
    __syncthreads();
    const int nc = min(s_ccnt, 64);

    float pnw[24];
    {
        const float* pn = g_pN + (size_t)p * D_;
        #pragma unroll
        for (int i = 0; i < 24; i++) pnw[i] = pn[lane + i * 32];
    }
    for (int ic = wid; ic < nc; ic += 8) {
        int col = s_cols[ic];
        const float* mcol = mb + (size_t)col * D_;
        float dot = 0.0f;
        #pragma unroll
        for (int i = 0; i < 24; i++) dot += pnw[i] * mcol[lane + i * 32];
        #pragma unroll
        for (int o = 16; o; o >>= 1) dot += __shfl_xor_sync(0xFFFFFFFFu, dot, o);
        if (lane == 0) s_val[ic] = dot * g_inv[col] - g_bias[col];
    }
    __syncthreads();
    if (tid == 0) {
        float bestE = -3.0e38f;
        for (int ic = 0; ic < nc; ic++) bestE = fmaxf(bestE, s_val[ic]);
        g_maxv[p] = f2ord(bestE);
    }
}

// ---------------- kernel 5: finalize ----------------------------------------
__global__ void finalize_kernel(float* __restrict__ out) {
    int b = threadIdx.x;
    if (b >= B_) return;
    float mx = -3.0e38f;
    #pragma unroll 7
    for (int j = 0; j < P_PER_B; j++) {
        int p = b * P_PER_B + j;
        float v  = ord2f(g_maxv[p]);
        float d2 = g_p2[p] - 2.0f * v;
        mx = fmaxf(mx, d2);
    }
    out[b] = sqrtf(fmaxf(mx, 1e-12f));
}

// ---------------- launch -----------------------------------------------------
extern "C" void kernel_launch(void* const* d_in, const int* in_sizes, int n_in,
                              void* d_out, int out_size) {
    (void)in_sizes; (void)n_in; (void)out_size;
    const float* tokens = (const float*)d_in[0];
    const float* mb     = (const float*)d_in[1];
    float* out          = (float*)d_out;

    norm_patches_kernel<<<NP_PAD, 256>>>(tokens);
    mb_convert_kernel<<<NM_PAD / 8, 256>>>(mb);

    cudaFuncSetAttribute(gemm_imma_kernel,
                         cudaFuncAttributeMaxDynamicSharedMemorySize, SM_TOTAL);
    dim3 grid(NP_PAD / BM, NM_PAD / BN);   // (25, 782)
    gemm_imma_kernel<<<grid, NTHR, SM_TOTAL>>>();

    rescore_kernel<<<NP, 256>>>(mb);
    finalize_kernel<<<1, 64>>>(out);
}

// round 8
// speedup vs baseline: 3.0037x; 1.0391x over previous
#include <cuda_runtime.h>
#include <math.h>
#include <limits.h>
#include <stdint.h>

// ---------------- problem shape ----------------
#define B_      64
#define TOK     50
#define P_PER_B 49
#define NP      3136
#define NP_PAD  3200      // 25 * 128
#define D_      768
#define NM      100000
#define NM_PAD  100096    // 782 * 128
#define NTILE   782

// ---------------- GEMM tiling ------------------
#define BM 128
#define BN 128
#define KCB 128           // K bytes per chunk (= 128B rows, SW128 atom)
#define NCHUNK 6
#define NTHR 256          // 8 warps: 2(M) x 4(N), warp tile 64x32

// SMEM: 3 stages x (A 16KB + B 16KB) = 96KB, then scalars
#define SM_A(s) ((s) * 16384)
#define SM_B(s) (49152 + (s) * 16384)
#define SM_SA   98304     // 128 f32
#define SM_C1   98816
#define SM_BIAS 99328
#define SM_RED  99840     // 128*4 u64 = 4096
#define SM_TOTAL (99840 + 4096)   // 103936 B

#define MARGIN 5.0e-3f

// ---------------- scratch ----------------------
__device__ int8_t g_pA8[(size_t)NP_PAD * D_];
__device__ int8_t g_mbB8[(size_t)NM_PAD * D_];
__device__ float  g_pN[(size_t)NP * D_];
__device__ float  g_sa[NP_PAD];
__device__ float  g_c1[NM_PAD];
__device__ float  g_inv[NM_PAD];
__device__ float  g_bias[NM_PAD];
__device__ float  g_p2[NP];
__device__ unsigned long long g_tile[(size_t)NP_PAD * NTILE];
__device__ int    g_maxv[NP];

// ---------------- helpers ----------------------
__device__ __forceinline__ int f2ord(float f) {
    int i = __float_as_int(f);
    return (i >= 0) ? i : (i ^ 0x7FFFFFFF);
}
__device__ __forceinline__ float ord2f(int i) {
    return __int_as_float((i >= 0) ? i : (i ^ 0x7FFFFFFF));
}
__device__ __forceinline__ uint32_t enc(float v) { return (uint32_t)f2ord(v) ^ 0x80000000u; }
__device__ __forceinline__ float dec(uint32_t k) { return ord2f((int)(k ^ 0x80000000u)); }

__device__ __forceinline__ uint32_t smem_u32(const void* p) {
    uint32_t a;
    asm("{ .reg .u64 t; cvta.to.shared.u64 t, %1; cvt.u32.u64 %0, t; }" : "=r"(a) : "l"(p));
    return a;
}
__device__ __forceinline__ void cp_async16(uint32_t dst, const void* src) {
    asm volatile("cp.async.cg.shared.global [%0], [%1], 16;" :: "r"(dst), "l"(src));
}
#define CP_COMMIT() asm volatile("cp.async.commit_group;" ::: "memory")
#define CP_WAIT0()  asm volatile("cp.async.wait_group 0;" ::: "memory")
#define CP_WAIT1()  asm volatile("cp.async.wait_group 1;" ::: "memory")

__device__ __forceinline__ uint32_t sw128(uint32_t off) {
    return off ^ ((off >> 3) & 0x70);
}
__device__ __forceinline__ void ldmat_x4(uint32_t* r, uint32_t addr) {
    asm volatile("ldmatrix.sync.aligned.m8n8.x4.shared.b16 {%0,%1,%2,%3}, [%4];"
        : "=r"(r[0]), "=r"(r[1]), "=r"(r[2]), "=r"(r[3]) : "r"(addr));
}
__device__ __forceinline__ void imma16832(int* c, const uint32_t* a, const uint32_t* b) {
    asm volatile("mma.sync.aligned.m16n8k32.row.col.s32.s8.s8.s32 "
        "{%0,%1,%2,%3}, {%4,%5,%6,%7}, {%8,%9}, {%0,%1,%2,%3};"
        : "+r"(c[0]), "+r"(c[1]), "+r"(c[2]), "+r"(c[3])
        : "r"(a[0]), "r"(a[1]), "r"(a[2]), "r"(a[3]), "r"(b[0]), "r"(b[1]));
}
__device__ __forceinline__ int8_t q8(float v, float rq) {
    int q = __float2int_rn(v * rq);
    q = max(-127, min(127, q));
    return (int8_t)q;
}

// ---------------- kernel 1: normalize patches -> fp32 + int8 ---------------
__global__ void norm_patches_kernel(const float* __restrict__ tokens) {
    int pb = blockIdx.x, tid = threadIdx.x;
    int8_t* dst8 = g_pA8 + (size_t)pb * D_;
    if (pb >= NP) {
        dst8[tid] = 0; dst8[tid + 256] = 0; dst8[tid + 512] = 0;
        if (tid == 0) g_sa[pb] = 0.0f;
        return;
    }
    int b = pb / P_PER_B, j = pb % P_PER_B;
    const float* src = tokens + ((size_t)(b * TOK + 1 + j)) * D_;
    float v0 = src[tid], v1 = src[tid + 256], v2 = src[tid + 512];
    float s = v0 * v0 + v1 * v1 + v2 * v2;
    float a = fmaxf(fabsf(v0), fmaxf(fabsf(v1), fabsf(v2)));

    __shared__ float ws[8], wa[8];
    __shared__ float s_tot, s_amax;
    #pragma unroll
    for (int o = 16; o; o >>= 1) {
        s += __shfl_xor_sync(0xFFFFFFFFu, s, o);
        a = fmaxf(a, __shfl_xor_sync(0xFFFFFFFFu, a, o));
    }
    if ((tid & 31) == 0) { ws[tid >> 5] = s; wa[tid >> 5] = a; }
    __syncthreads();
    if (tid < 32) {
        float t = (tid < 8) ? ws[tid] : 0.0f;
        float m = (tid < 8) ? wa[tid] : 0.0f;
        #pragma unroll
        for (int o = 4; o; o >>= 1) {
            t += __shfl_xor_sync(0xFFFFFFFFu, t, o);
            m = fmaxf(m, __shfl_xor_sync(0xFFFFFFFFu, m, o));
        }
        if (tid == 0) { s_tot = t; s_amax = m; }
    }
    __syncthreads();
    float tot = s_tot;
    float inv = 1.0f / (sqrtf(tot) + 1e-12f);
    float amax_n = s_amax * inv;
    float rq = (amax_n > 0.0f) ? (127.0f / amax_n) : 0.0f;

    float* pn = g_pN + (size_t)pb * D_;
    float n0 = v0 * inv, n1 = v1 * inv, n2 = v2 * inv;
    pn[tid] = n0; pn[tid + 256] = n1; pn[tid + 512] = n2;
    dst8[tid]       = q8(n0, rq);
    dst8[tid + 256] = q8(n1, rq);
    dst8[tid + 512] = q8(n2, rq);
    if (tid == 0) {
        g_sa[pb] = amax_n / 127.0f;
        g_p2[pb] = tot * inv * inv;
    }
}

// ---------------- kernel 2: MB stats + int8 quantize ------------------------
__global__ void mb_convert_kernel(const float* __restrict__ mb) {
    int row  = blockIdx.x * 8 + (threadIdx.x >> 5);
    int lane = threadIdx.x & 31;
    if (row >= NM_PAD) return;
    uint32_t* dst = (uint32_t*)(g_mbB8 + (size_t)row * D_);
    if (row < NM) {
        const float4* r = (const float4*)(mb + (size_t)row * D_);
        float4 v[6]; float s = 0.0f, a = 0.0f;
        #pragma unroll
        for (int i = 0; i < 6; i++) {
            v[i] = r[lane + i * 32];
            s += v[i].x * v[i].x + v[i].y * v[i].y + v[i].z * v[i].z + v[i].w * v[i].w;
            a = fmaxf(a, fmaxf(fmaxf(fabsf(v[i].x), fabsf(v[i].y)),
                               fmaxf(fabsf(v[i].z), fabsf(v[i].w))));
        }
        #pragma unroll
        for (int o = 16; o; o >>= 1) {
            s += __shfl_xor_sync(0xFFFFFFFFu, s, o);
            a = fmaxf(a, __shfl_xor_sync(0xFFFFFFFFu, a, o));
        }
        float rq = (a > 0.0f) ? (127.0f / a) : 0.0f;
        #pragma unroll
        for (int i = 0; i < 6; i++) {
            uint32_t w = ((uint32_t)(uint8_t)q8(v[i].x, rq))
                       | ((uint32_t)(uint8_t)q8(v[i].y, rq) << 8)
                       | ((uint32_t)(uint8_t)q8(v[i].z, rq) << 16)
                       | ((uint32_t)(uint8_t)q8(v[i].w, rq) << 24);
            dst[lane + i * 32] = w;
        }
        if (lane == 0) {
            float inv = 1.0f / (sqrtf(s) + 1e-12f);
            g_inv[row]  = inv;
            g_bias[row] = 0.5f * s * inv * inv;
            g_c1[row]   = (a / 127.0f) * inv;
        }
    } else {
        #pragma unroll
        for (int i = 0; i < 6; i++) dst[lane + i * 32] = 0u;
        if (lane == 0) { g_inv[row] = 0.0f; g_bias[row] = 1e30f; g_c1[row] = 0.0f; }
    }
}

// ---------------- kernel 3: IMMA GEMM (ldmatrix, 3-stage pipeline) ----------
__global__ void __launch_bounds__(NTHR, 2)
gemm_imma_kernel() {
    extern __shared__ __align__(1024) char smem[];
    const uint32_t sbase = smem_u32(smem);
    const int tid  = threadIdx.x;
    const int wid  = tid >> 5;
    const int lane = tid & 31;
    const int p0 = blockIdx.x * BM;
    const int n0 = blockIdx.y * BN;
    const int wm = (wid & 1) * 64;
    const int wn_idx = wid >> 1;
    const int wn = wn_idx * 32;
    const int g  = lane >> 2;
    const int tq = lane & 3;

    float* sa_s   = (float*)(smem + SM_SA);
    float* c1_s   = (float*)(smem + SM_C1);
    float* bias_s = (float*)(smem + SM_BIAS);
    unsigned long long* red = (unsigned long long*)(smem + SM_RED);

    if (tid < 128) {
        sa_s[tid]   = g_sa[p0 + tid];
        c1_s[tid]   = g_c1[n0 + tid];
        bias_s[tid] = g_bias[n0 + tid];
    }

    const int8_t* gA = g_pA8  + (size_t)p0 * D_;
    const int8_t* gB = g_mbB8 + (size_t)n0 * D_;
    const int ld_r = tid >> 3;        // base row, +32 per iter
    const int ld_c = tid & 7;         // 16B granule in 128B row
    const uint32_t ld_off0 = sw128((uint32_t)(ld_r * 128 + ld_c * 16));
    const uint32_t ld_off1 = sw128((uint32_t)((ld_r + 32) * 128 + ld_c * 16));
    const uint32_t ld_off2 = sw128((uint32_t)((ld_r + 64) * 128 + ld_c * 16));
    const uint32_t ld_off3 = sw128((uint32_t)((ld_r + 96) * 128 + ld_c * 16));

    // prologue: chunks 0,1 -> stages 0,1 (two groups in flight)
    #pragma unroll
    for (int pc = 0; pc < 2; pc++) {
        const int8_t* cA = gA + (size_t)pc * KCB;
        const int8_t* cB = gB + (size_t)pc * KCB;
        const uint32_t dA = sbase + SM_A(pc);
        const uint32_t dB = sbase + SM_B(pc);
        const size_t ga0 = (size_t)ld_r * D_ + ld_c * 16;
        cp_async16(dA + ld_off0, cA + ga0);
        cp_async16(dA + ld_off1, cA + ga0 + (size_t)32 * D_);
        cp_async16(dA + ld_off2, cA + ga0 + (size_t)64 * D_);
        cp_async16(dA + ld_off3, cA + ga0 + (size_t)96 * D_);
        cp_async16(dB + ld_off0, cB + ga0);
        cp_async16(dB + ld_off1, cB + ga0 + (size_t)32 * D_);
        cp_async16(dB + ld_off2, cB + ga0 + (size_t)64 * D_);
        cp_async16(dB + ld_off3, cB + ga0 + (size_t)96 * D_);
        CP_COMMIT();
    }

    // ldmatrix lane-address components
    const uint32_t aRow = (uint32_t)(wm + (lane & 15)) * 128;
    const uint32_t aCol = (uint32_t)((lane >> 4) << 4);
    const uint32_t bRow = (uint32_t)(wn + (lane & 7) + ((lane >> 4) << 3)) * 128;
    const uint32_t bCol = (uint32_t)(((lane >> 3) & 1) << 4);

    int acc[4][4][4];
    #pragma unroll
    for (int i = 0; i < 4; i++)
        #pragma unroll
        for (int j = 0; j < 4; j++)
            #pragma unroll
            for (int q = 0; q < 4; q++) acc[i][j][q] = 0;

    #pragma unroll 1
    for (int kc = 0; kc < NCHUNK; kc++) {
        const int s = kc % 3;
        const uint32_t sA = sbase + SM_A(s);
        const uint32_t sB = sbase + SM_B(s);

        // chunk kc's group must be complete; chunk kc+1's may stay in flight
        if (kc + 1 < NCHUNK) { CP_WAIT1(); } else { CP_WAIT0(); }
        __syncthreads();   // also: all warps finished reading stage (kc+2)%3 (iter kc-1)

        if (kc + 2 < NCHUNK) {
            const int d = (kc + 2) % 3;
            const uint32_t dA = sbase + SM_A(d);
            const uint32_t dB = sbase + SM_B(d);
            const int8_t* cA = gA + (size_t)(kc + 2) * KCB;
            const int8_t* cB = gB + (size_t)(kc + 2) * KCB;
            const size_t ga0 = (size_t)ld_r * D_ + ld_c * 16;
            cp_async16(dA + ld_off0, cA + ga0);
            cp_async16(dA + ld_off1, cA + ga0 + (size_t)32 * D_);
            cp_async16(dA + ld_off2, cA + ga0 + (size_t)64 * D_);
            cp_async16(dA + ld_off3, cA + ga0 + (size_t)96 * D_);
            cp_async16(dB + ld_off0, cB + ga0);
            cp_async16(dB + ld_off1, cB + ga0 + (size_t)32 * D_);
            cp_async16(dB + ld_off2, cB + ga0 + (size_t)64 * D_);
            cp_async16(dB + ld_off3, cB + ga0 + (size_t)96 * D_);
            CP_COMMIT();
        }

        #pragma unroll
        for (int ks = 0; ks < 4; ks++) {
            const uint32_t kb = (uint32_t)(ks * 32);
            uint32_t af[4][4], bf[2][4];
            #pragma unroll
            for (int tm = 0; tm < 4; tm++)
                ldmat_x4(af[tm], sA + sw128(aRow + (uint32_t)(tm * 16 * 128) + kb + aCol));
            #pragma unroll
            for (int bn = 0; bn < 2; bn++)
                ldmat_x4(bf[bn], sB + sw128(bRow + (uint32_t)(bn * 16 * 128) + kb + bCol));
            #pragma unroll
            for (int tm = 0; tm < 4; tm++)
                #pragma unroll
                for (int tn = 0; tn < 4; tn++)
                    imma16832(acc[tm][tn], af[tm], bf[tn >> 1] + (tn & 1) * 2);
        }
    }
    __syncthreads();

    // epilogue: per-row (max,col) packed u64, per-tile store
    #pragma unroll
    for (int tm = 0; tm < 4; tm++) {
        #pragma unroll
        for (int half = 0; half < 2; half++) {
            int rl = wm + tm * 16 + g + half * 8;
            float sar = sa_s[rl];
            unsigned long long best = 0ull;
            #pragma unroll
            for (int tn = 0; tn < 4; tn++) {
                int cl = wn + tn * 8 + tq * 2;
                float v0 = (float)acc[tm][tn][half * 2 + 0] * (sar * c1_s[cl])     - bias_s[cl];
                float v1 = (float)acc[tm][tn][half * 2 + 1] * (sar * c1_s[cl + 1]) - bias_s[cl + 1];
                unsigned long long k0 = ((unsigned long long)enc(v0) << 32) | (uint32_t)(n0 + cl);
                unsigned long long k1 = ((unsigned long long)enc(v1) << 32) | (uint32_t)(n0 + cl + 1);
                if (k0 > best) best = k0;
                if (k1 > best) best = k1;
            }
            unsigned long long o1 = __shfl_xor_sync(0xFFFFFFFFu, best, 1);
            if (o1 > best) best = o1;
            unsigned long long o2 = __shfl_xor_sync(0xFFFFFFFFu, best, 2);
            if (o2 > best) best = o2;
            if (tq == 0) red[rl * 4 + wn_idx] = best;
        }
    }
    __syncthreads();

    if (tid < BM) {
        unsigned long long m = red[tid * 4];
        #pragma unroll
        for (int j = 1; j < 4; j++)
            if (red[tid * 4 + j] > m) m = red[tid * 4 + j];
        g_tile[(size_t)(p0 + tid) * NTILE + blockIdx.y] = m;
    }
}

// ---------------- kernel 4: rescore (one CTA per patch) ---------------------
__global__ void __launch_bounds__(256)
rescore_kernel(const float* __restrict__ mb) {
    __shared__ unsigned long long s_bw[8];
    __shared__ int s_tiles[128];
    __shared__ int s_cols[64];
    __shared__ int s_tcnt, s_ccnt;
    __shared__ float s_thr;
    __shared__ float s_val[64];

    const int p = blockIdx.x;
    const int tid = threadIdx.x;
    const int wid = tid >> 5;
    const int lane = tid & 31;

    // --- 1. single-pass scan: keep tile keys in registers ---
    const unsigned long long* row = g_tile + (size_t)p * NTILE;
    unsigned long long vreg[4];
    #pragma unroll
    for (int i = 0; i < 4; i++) {
        int t = tid + i * 256;
        vreg[i] = (t < NTILE) ? row[t] : 0ull;
    }
    unsigned long long best = vreg[0];
    #pragma unroll
    for (int i = 1; i < 4; i++) if (vreg[i] > best) best = vreg[i];
    #pragma unroll
    for (int o = 16; o; o >>= 1) {
        unsigned long long v = __shfl_xor_sync(0xFFFFFFFFu, best, o);
        if (v > best) best = v;
    }
    if (lane == 0) s_bw[wid] = best;
    if (tid == 0) { s_tcnt = 0; s_ccnt = 0; }
    __syncthreads();
    if (tid == 0) {
        unsigned long long m = s_bw[0];
        #pragma unroll
        for (int w = 1; w < 8; w++) if (s_bw[w] > m) m = s_bw[w];
        s_thr = dec((uint32_t)(m >> 32)) - MARGIN;
    }
    __syncthreads();
    const float thr = s_thr;
    const uint32_t thrkey = enc(thr);

    // --- 2. candidate tiles from registers ---
    #pragma unroll
    for (int i = 0; i < 4; i++) {
        int t = tid + i * 256;
        if (t < NTILE && (uint32_t)(vreg[i] >> 32) >= thrkey) {
            int ix = atomicAdd(&s_tcnt, 1);
            if (ix < 128) s_tiles[ix] = t;
        }
    }
    __syncthreads();
    const int nt = min(s_tcnt, 128);
    const int ncols = nt * 128;

    // --- 3. int8 filter, 8 cols in flight per warp ---
    const float sa = g_sa[p];
    int paw[6];
    {
        const int* pa = (const int*)(g_pA8 + (size_t)p * D_);
        #pragma unroll
        for (int i = 0; i < 6; i++) paw[i] = pa[lane + i * 32];
    }
    for (int base = wid * 8; base < ncols; base += 64) {
        int acc8[8];
        int col8[8];
        #pragma unroll
        for (int j = 0; j < 8; j++) {
            int idx = base + j;
            int t = s_tiles[idx >> 7];
            col8[j] = t * 128 + (idx & 127);
            acc8[j] = 0;
            const int* bc = (const int*)(g_mbB8 + (size_t)col8[j] * D_);
            #pragma unroll
            for (int i = 0; i < 6; i++)
                acc8[j] = __dp4a(paw[i], bc[lane + i * 32], acc8[j]);
        }
        #pragma unroll
        for (int j = 0; j < 8; j++) {
            int dot = __reduce_add_sync(0xFFFFFFFFu, acc8[j]);
            if (lane == 0) {
                int col = col8[j];
                float vq = (float)dot * sa * g_c1[col] - g_bias[col];
                if (vq >= thr) {
                    int ix = atomicAdd(&s_ccnt, 1);
                    if (ix < 64) s_cols[ix] = col;
                }
            }
        }
    }
    __syncthreads();
    const int nc = min(s_ccnt, 64);

    // --- 4. exact fp32 rescore of survivors ---
    float pnw[24];
    {
        const float* pn = g_pN + (size_t)p * D_;
        #pragma unroll
        for (int i = 0; i < 24; i++) pnw[i] = pn[lane + i * 32];
    }
    for (int ic = wid; ic < nc; ic += 8) {
        int col = s_cols[ic];
        const float* mcol = mb + (size_t)col * D_;
        float dot = 0.0f;
        #pragma unroll
        for (int i = 0; i < 24; i++) dot += pnw[i] * mcol[lane + i * 32];
        #pragma unroll
        for (int o = 16; o; o >>= 1) dot += __shfl_xor_sync(0xFFFFFFFFu, dot, o);
        if (lane == 0) s_val[ic] = dot * g_inv[col] - g_bias[col];
    }
    __syncthreads();
    if (tid == 0) {
        float bestE = -3.0e38f;
        for (int ic = 0; ic < nc; ic++) bestE = fmaxf(bestE, s_val[ic]);
        g_maxv[p] = f2ord(bestE);
    }
}

// ---------------- kernel 5: finalize ----------------------------------------
__global__ void finalize_kernel(float* __restrict__ out) {
    int b = threadIdx.x;
    if (b >= B_) return;
    float mx = -3.0e38f;
    #pragma unroll 7
    for (int j = 0; j < P_PER_B; j++) {
        int p = b * P_PER_B + j;
        float v  = ord2f(g_maxv[p]);
        float d2 = g_p2[p] - 2.0f * v;
        mx = fmaxf(mx, d2);
    }
    out[b] = sqrtf(fmaxf(mx, 1e-12f));
}

// ---------------- launch -----------------------------------------------------
extern "C" void kernel_launch(void* const* d_in, const int* in_sizes, int n_in,
                              void* d_out, int out_size) {
    (void)in_sizes; (void)n_in; (void)out_size;
    const float* tokens = (const float*)d_in[0];
    const float* mb     = (const float*)d_in[1];
    float* out          = (float*)d_out;

    norm_patches_kernel<<<NP_PAD, 256>>>(tokens);
    mb_convert_kernel<<<NM_PAD / 8, 256>>>(mb);

    cudaFuncSetAttribute(gemm_imma_kernel,
                         cudaFuncAttributeMaxDynamicSharedMemorySize, SM_TOTAL);
    dim3 grid(NP_PAD / BM, NM_PAD / BN);   // (25, 782)
    gemm_imma_kernel<<<grid, NTHR, SM_TOTAL>>>();

    rescore_kernel<<<NP, 256>>>(mb);
    finalize_kernel<<<1, 64>>>(out);
}